// round 4
// baseline (speedup 1.0000x reference)
#include <cuda_runtime.h>
#include <cuda_bf16.h>

// Problem dims
#define BB    32
#define SS    512
#define WIN   5
#define EMB   300
#define HH    300
#define K1    1500        // EMB*WIN
#define NOUT  128
#define MROWS (BB*SS)     // 16384

// ------------------------------------------------------------------
// Scratch (static device globals)
// ------------------------------------------------------------------
__device__ float g_A [(size_t)MROWS * HH];   // pre-activation (A1 then A2)
__device__ float g_H1[(size_t)MROWS * HH];   // layer1 hidden states [s*32+b][300]
__device__ float g_H2[(size_t)MROWS * HH];   // layer2 hidden states

// ------------------------------------------------------------------
// f32x2 helpers
// ------------------------------------------------------------------
__device__ __forceinline__ void ffma2(unsigned long long &d,
                                      unsigned long long a,
                                      unsigned long long b) {
    asm("fma.rn.f32x2 %0, %1, %2, %0;" : "+l"(d) : "l"(a), "l"(b));
}
__device__ __forceinline__ unsigned long long pack2(float lo, float hi) {
    unsigned long long r;
    asm("mov.b64 %0, {%1, %2};" : "=l"(r) : "f"(lo), "f"(hi));
    return r;
}
__device__ __forceinline__ void unpack2(unsigned long long v, float &lo, float &hi) {
    asm("mov.b64 {%0, %1}, %2;" : "=f"(lo), "=f"(hi) : "l"(v));
}
__device__ __forceinline__ unsigned smem_u32(const void *p) {
    unsigned a;
    asm("{ .reg .u64 t; cvta.to.shared.u64 t, %1; cvt.u32.u64 %0, t; }"
        : "=r"(a) : "l"(p));
    return a;
}
// tanh via MUFU: 1 - 2/(exp2(2x*log2e)+1). abs err ~1e-7, no division.
__device__ __forceinline__ float tanh_fast(float x) {
    float e;
    asm("ex2.approx.f32 %0, %1;" : "=f"(e) : "f"(x * 2.88539008177792681f));
    float r;
    asm("rcp.approx.f32 %0, %1;" : "=f"(r) : "f"(e + 1.0f));
    return fmaf(-2.0f, r, 1.0f);
}

// ------------------------------------------------------------------
// GEMM (plain): C[m][n] = sum_k A[m][k]*Bw[n][k] + b1[n] (+ b2[n])
// BM=128, BN=64, BK=16, 256 threads, 4x8 thread tile via f32x2.
// ------------------------------------------------------------------
template <bool PERM>
__global__ __launch_bounds__(256)
void gemm_nt(const float *__restrict__ A, const float *__restrict__ Bw,
             const float *__restrict__ b1, const float *__restrict__ b2,
             float *__restrict__ C, int M, int N, int K, int ldc) {
    __shared__ __align__(16) float As[16][132];
    __shared__ __align__(16) float Bs[16][68];

    const int tid = threadIdx.x;
    const int m0 = blockIdx.y * 128;
    const int n0 = blockIdx.x * 64;
    const int tx = tid & 7;
    const int ty = tid >> 3;
    const int a_r = tid >> 2;
    const int a_k = (tid & 3) * 4;

    unsigned long long acc[4][4];
#pragma unroll
    for (int i = 0; i < 4; i++)
#pragma unroll
        for (int j = 0; j < 4; j++) acc[i][j] = 0ULL;

    const int KT = (K + 15) >> 4;
    for (int kt = 0; kt < KT; kt++) {
        int k0 = kt * 16;
        float4 av0 = make_float4(0.f, 0.f, 0.f, 0.f);
        float4 av1 = av0, bv = av0;
        int kk = k0 + a_k;
        if (kk < K) {
            av0 = *reinterpret_cast<const float4 *>(A + (size_t)(m0 + a_r) * K + kk);
            av1 = *reinterpret_cast<const float4 *>(A + (size_t)(m0 + a_r + 64) * K + kk);
            if (n0 + a_r < N)
                bv = *reinterpret_cast<const float4 *>(Bw + (size_t)(n0 + a_r) * K + kk);
        }
        __syncthreads();
        As[a_k + 0][a_r] = av0.x; As[a_k + 1][a_r] = av0.y;
        As[a_k + 2][a_r] = av0.z; As[a_k + 3][a_r] = av0.w;
        As[a_k + 0][a_r + 64] = av1.x; As[a_k + 1][a_r + 64] = av1.y;
        As[a_k + 2][a_r + 64] = av1.z; As[a_k + 3][a_r + 64] = av1.w;
        Bs[a_k + 0][a_r] = bv.x; Bs[a_k + 1][a_r] = bv.y;
        Bs[a_k + 2][a_r] = bv.z; Bs[a_k + 3][a_r] = bv.w;
        __syncthreads();

#pragma unroll
        for (int k = 0; k < 16; k++) {
            float4 a4 = *reinterpret_cast<const float4 *>(&As[k][ty * 4]);
            const ulonglong2 *bp =
                reinterpret_cast<const ulonglong2 *>(&Bs[k][tx * 8]);
            ulonglong2 bA = bp[0], bB = bp[1];
            unsigned long long a0 = pack2(a4.x, a4.x);
            unsigned long long a1 = pack2(a4.y, a4.y);
            unsigned long long a2 = pack2(a4.z, a4.z);
            unsigned long long a3 = pack2(a4.w, a4.w);
            ffma2(acc[0][0], a0, bA.x); ffma2(acc[0][1], a0, bA.y);
            ffma2(acc[0][2], a0, bB.x); ffma2(acc[0][3], a0, bB.y);
            ffma2(acc[1][0], a1, bA.x); ffma2(acc[1][1], a1, bA.y);
            ffma2(acc[1][2], a1, bB.x); ffma2(acc[1][3], a1, bB.y);
            ffma2(acc[2][0], a2, bA.x); ffma2(acc[2][1], a2, bA.y);
            ffma2(acc[2][2], a2, bB.x); ffma2(acc[2][3], a2, bB.y);
            ffma2(acc[3][0], a3, bA.x); ffma2(acc[3][1], a3, bA.y);
            ffma2(acc[3][2], a3, bB.x); ffma2(acc[3][3], a3, bB.y);
        }
    }

    float bias[8];
#pragma unroll
    for (int jj = 0; jj < 8; jj++) {
        int n = n0 + tx * 8 + jj;
        bias[jj] = (n < N) ? (b1[n] + (b2 ? b2[n] : 0.f)) : 0.f;
    }
#pragma unroll
    for (int i = 0; i < 4; i++) {
        int m = m0 + ty * 4 + i;
        int row = PERM ? ((m & 31) * SS + (m >> 5)) : m;
        float *cp = C + (size_t)row * ldc;
#pragma unroll
        for (int j = 0; j < 4; j++) {
            int n = n0 + tx * 8 + 2 * j;
            float lo, hi;
            unpack2(acc[i][j], lo, hi);
            if (n < N)     cp[n]     = lo + bias[2 * j];
            if (n + 1 < N) cp[n + 1] = hi + bias[2 * j + 1];
        }
    }
}

// ------------------------------------------------------------------
// GEMM with fused embedding+relu A-path (G1 only):
// A[m][k] = relu(emb[ x[b,s,kk/300] ][ kk%300 ]),  m = s*32+b, K=1500.
// Avoids materializing the 98MB XE buffer; emb (38MB) lives in L2.
// ------------------------------------------------------------------
__global__ __launch_bounds__(256)
void gemm_embed(const int *__restrict__ x, const float *__restrict__ emb,
                const float *__restrict__ Bw, const float *__restrict__ b1,
                const float *__restrict__ b2, float *__restrict__ C) {
    const int M = MROWS, N = HH, K = K1, ldc = HH;
    __shared__ __align__(16) float As[16][132];
    __shared__ __align__(16) float Bs[16][68];
    __shared__ int idx[128][WIN];

    const int tid = threadIdx.x;
    const int m0 = blockIdx.y * 128;
    const int n0 = blockIdx.x * 64;
    const int tx = tid & 7;
    const int ty = tid >> 3;
    const int a_r = tid >> 2;
    const int a_k = (tid & 3) * 4;

    // load the 128x5 token indices for this M tile
    for (int i = tid; i < 128 * WIN; i += 256) {
        int r = i / WIN, w = i - (i / WIN) * WIN;
        int m = m0 + r, s = m >> 5, bb = m & 31;
        idx[r][w] = x[(bb * SS + s) * WIN + w];
    }
    __syncthreads();

    unsigned long long acc[4][4];
#pragma unroll
    for (int i = 0; i < 4; i++)
#pragma unroll
        for (int j = 0; j < 4; j++) acc[i][j] = 0ULL;

    const int KT = (K + 15) >> 4;   // 94
    for (int kt = 0; kt < KT; kt++) {
        int k0 = kt * 16;
        float4 av0 = make_float4(0.f, 0.f, 0.f, 0.f);
        float4 av1 = av0, bv = av0;
        int kk = k0 + a_k;
        if (kk < K) {
            int w = kk / EMB;
            int e = kk - w * EMB;           // multiple of 4; float4 stays in-row
            av0 = *reinterpret_cast<const float4 *>(
                emb + (size_t)idx[a_r][w] * EMB + e);
            av1 = *reinterpret_cast<const float4 *>(
                emb + (size_t)idx[a_r + 64][w] * EMB + e);
            av0.x = fmaxf(av0.x, 0.f); av0.y = fmaxf(av0.y, 0.f);
            av0.z = fmaxf(av0.z, 0.f); av0.w = fmaxf(av0.w, 0.f);
            av1.x = fmaxf(av1.x, 0.f); av1.y = fmaxf(av1.y, 0.f);
            av1.z = fmaxf(av1.z, 0.f); av1.w = fmaxf(av1.w, 0.f);
            if (n0 + a_r < N)
                bv = *reinterpret_cast<const float4 *>(Bw + (size_t)(n0 + a_r) * K + kk);
        }
        __syncthreads();
        As[a_k + 0][a_r] = av0.x; As[a_k + 1][a_r] = av0.y;
        As[a_k + 2][a_r] = av0.z; As[a_k + 3][a_r] = av0.w;
        As[a_k + 0][a_r + 64] = av1.x; As[a_k + 1][a_r + 64] = av1.y;
        As[a_k + 2][a_r + 64] = av1.z; As[a_k + 3][a_r + 64] = av1.w;
        Bs[a_k + 0][a_r] = bv.x; Bs[a_k + 1][a_r] = bv.y;
        Bs[a_k + 2][a_r] = bv.z; Bs[a_k + 3][a_r] = bv.w;
        __syncthreads();

#pragma unroll
        for (int k = 0; k < 16; k++) {
            float4 a4 = *reinterpret_cast<const float4 *>(&As[k][ty * 4]);
            const ulonglong2 *bp =
                reinterpret_cast<const ulonglong2 *>(&Bs[k][tx * 8]);
            ulonglong2 bA = bp[0], bB = bp[1];
            unsigned long long a0 = pack2(a4.x, a4.x);
            unsigned long long a1 = pack2(a4.y, a4.y);
            unsigned long long a2 = pack2(a4.z, a4.z);
            unsigned long long a3 = pack2(a4.w, a4.w);
            ffma2(acc[0][0], a0, bA.x); ffma2(acc[0][1], a0, bA.y);
            ffma2(acc[0][2], a0, bB.x); ffma2(acc[0][3], a0, bB.y);
            ffma2(acc[1][0], a1, bA.x); ffma2(acc[1][1], a1, bA.y);
            ffma2(acc[1][2], a1, bB.x); ffma2(acc[1][3], a1, bB.y);
            ffma2(acc[2][0], a2, bA.x); ffma2(acc[2][1], a2, bA.y);
            ffma2(acc[2][2], a2, bB.x); ffma2(acc[2][3], a2, bB.y);
            ffma2(acc[3][0], a3, bA.x); ffma2(acc[3][1], a3, bA.y);
            ffma2(acc[3][2], a3, bB.x); ffma2(acc[3][3], a3, bB.y);
        }
    }

    float bias[8];
#pragma unroll
    for (int jj = 0; jj < 8; jj++) {
        int n = n0 + tx * 8 + jj;
        bias[jj] = (n < N) ? (b1[n] + b2[n]) : 0.f;
    }
#pragma unroll
    for (int i = 0; i < 4; i++) {
        int m = m0 + ty * 4 + i;
        float *cp = C + (size_t)m * ldc;
#pragma unroll
        for (int j = 0; j < 4; j++) {
            int n = n0 + tx * 8 + 2 * j;
            float lo, hi;
            unpack2(acc[i][j], lo, hi);
            if (n < N)     cp[n]     = lo + bias[2 * j];
            if (n + 1 < N) cp[n + 1] = hi + bias[2 * j + 1];
        }
    }
}

// ------------------------------------------------------------------
// Recurrence: one batch element per 4-CTA cluster (32 clusters, 128 SMs).
// h_t = tanh(A[t,b,:] + W_hh @ h_{t-1}); W slice (75x300) in registers.
// Handshake: point-to-point mbarriers (st.shared::cluster + remote
// release-arrive, acquire try_wait). No barrier.cluster inside the loop.
// ------------------------------------------------------------------
__global__ void __cluster_dims__(4, 1, 1) __launch_bounds__(320)
rec_kernel(const float *__restrict__ W, const float *__restrict__ A,
           float *__restrict__ Hout) {
    __shared__ __align__(16) float hs[2][4][80];   // h_t lives in hs[t&1]
    __shared__ float ps[4][80];
    __shared__ __align__(8) unsigned long long mbar[2];

    const int tid  = threadIdx.x;
    const int rank = blockIdx.x & 3;
    const int b    = blockIdx.x >> 2;
    const int kc   = tid / 75;
    const int jr   = tid % 75;
    const bool active = tid < 300;

    // W slice -> registers as f32x2 pairs (76th element zero-padded)
    unsigned long long w2[38];
    if (active) {
        const float *wp = W + (size_t)(rank * 75 + jr) * HH + kc * 75;
#pragma unroll
        for (int i = 0; i < 37; i++) w2[i] = pack2(wp[2 * i], wp[2 * i + 1]);
        w2[37] = pack2(wp[74], 0.f);
    }
    for (int i = tid; i < 2 * 4 * 80; i += blockDim.x)
        (&hs[0][0][0])[i] = 0.f;
    if (tid == 0) {
        unsigned m0 = smem_u32(&mbar[0]), m1 = smem_u32(&mbar[1]);
        asm volatile("mbarrier.init.shared.b64 [%0], 225;" :: "r"(m0) : "memory");
        asm volatile("mbarrier.init.shared.b64 [%0], 225;" :: "r"(m1) : "memory");
    }
    __syncthreads();
    asm volatile("barrier.cluster.arrive.aligned;" ::: "memory");
    asm volatile("barrier.cluster.wait.aligned;" ::: "memory");

    const float *arow = A + (size_t)b * HH + rank * 75;
    float *hrow = Hout + (size_t)b * HH + rank * 75;

    float a_cur = (tid < 75) ? arow[tid] : 0.f;

    for (int t = 0; t < SS; t++) {
        // prefetch next step's A (hidden under this step's critical path)
        float a_nxt = 0.f;
        if (tid < 75 && t + 1 < SS)
            a_nxt = arow[(size_t)(t + 1) * BB * HH + tid];

        // wait for peer h chunks of step t-1 (own chunk is local; skip)
        if (t > 0 && active && kc != rank) {
            unsigned mb = smem_u32(&mbar[(t - 1) & 1]);
            unsigned par = ((t - 1) >> 1) & 1;
            asm volatile(
                "{\n\t.reg .pred P;\n"
                "RW%=:\n\t"
                "mbarrier.try_wait.parity.acquire.cluster.shared::cta.b64 P, [%0], %1;\n\t"
                "@!P bra RW%=;\n\t}"
                :: "r"(mb), "r"(par) : "memory");
        }

        if (active) {
            const int rb = (t & 1) ^ 1;   // h_{t-1} buffer
            const ulonglong2 *hp2 =
                reinterpret_cast<const ulonglong2 *>(&hs[rb][kc][0]);
            unsigned long long acc0 = 0ULL, acc1 = 0ULL;
#pragma unroll
            for (int k = 0; k < 19; k++) {
                ulonglong2 hv = hp2[k];
                if (k & 1) { ffma2(acc1, w2[2 * k], hv.x); ffma2(acc1, w2[2 * k + 1], hv.y); }
                else       { ffma2(acc0, w2[2 * k], hv.x); ffma2(acc0, w2[2 * k + 1], hv.y); }
            }
            float l0, h0, l1, h1;
            unpack2(acc0, l0, h0); unpack2(acc1, l1, h1);
            ps[kc][jr] = (l0 + h0) + (l1 + h1);
        }
        __syncthreads();

        if (tid < 75) {
            float s = ps[0][tid] + ps[1][tid] + ps[2][tid] + ps[3][tid] + a_cur;
            float hv = tanh_fast(s);
            hrow[(size_t)t * BB * HH + tid] = hv;
            const int wb = t & 1;
            hs[wb][rank][tid] = hv;                     // local copy
            unsigned loc_h = smem_u32(&hs[wb][rank][tid]);
            unsigned loc_m = smem_u32(&mbar[wb]);
#pragma unroll
            for (int d = 1; d < 4; d++) {
                int r = (rank + d) & 3;
                asm volatile(
                    "{ .reg .b32 ra; mapa.shared::cluster.u32 ra, %0, %1;"
                    "  st.shared::cluster.f32 [ra], %2; }"
                    :: "r"(loc_h), "r"(r), "f"(hv) : "memory");
            }
#pragma unroll
            for (int d = 1; d < 4; d++) {
                int r = (rank + d) & 3;
                asm volatile(
                    "{ .reg .b32 ra; mapa.shared::cluster.u32 ra, %0, %1;"
                    "  mbarrier.arrive.release.cluster.shared::cluster.b64 _, [ra]; }"
                    :: "r"(loc_m), "r"(r) : "memory");
            }
        }
        a_cur = a_nxt;
        __syncthreads();   // local h visible to own CTA before next step
    }

    // don't exit while peers' remote ops targeting our SMEM may be in flight
    asm volatile("barrier.cluster.arrive.aligned;" ::: "memory");
    asm volatile("barrier.cluster.wait.aligned;" ::: "memory");
}

// ------------------------------------------------------------------
// Launch sequence
// ------------------------------------------------------------------
extern "C" void kernel_launch(void *const *d_in, const int *in_sizes, int n_in,
                              void *d_out, int out_size) {
    const int   *x     = (const int *)d_in[0];
    const float *emb   = (const float *)d_in[1];
    const float *W_ih1 = (const float *)d_in[2];
    const float *W_hh1 = (const float *)d_in[3];
    const float *b_ih1 = (const float *)d_in[4];
    const float *b_hh1 = (const float *)d_in[5];
    const float *W_ih2 = (const float *)d_in[6];
    const float *W_hh2 = (const float *)d_in[7];
    const float *b_ih2 = (const float *)d_in[8];
    const float *b_hh2 = (const float *)d_in[9];
    const float *fc1_w = (const float *)d_in[10];
    const float *fc1_b = (const float *)d_in[11];
    const float *fc2_w = (const float *)d_in[12];
    const float *fc2_b = (const float *)d_in[13];
    float *out = (float *)d_out;

    float *a, *h1, *h2;
    cudaGetSymbolAddress((void **)&a,  g_A);
    cudaGetSymbolAddress((void **)&h1, g_H1);
    cudaGetSymbolAddress((void **)&h2, g_H2);

    // 1) A1 = relu(embed(x)) @ W_ih1^T + (b_ih1 + b_hh1)  (fused embed)
    {
        dim3 grid((HH + 63) / 64, MROWS / 128);
        gemm_embed<<<grid, 256>>>(x, emb, W_ih1, b_ih1, b_hh1, a);
    }
    // 2) layer-1 recurrence -> H1
    rec_kernel<<<128, 320>>>(W_hh1, a, h1);

    // 3) A2 = H1 @ W_ih2^T + (b_ih2 + b_hh2)
    {
        dim3 grid((HH + 63) / 64, MROWS / 128);
        gemm_nt<false><<<grid, 256>>>(h1, W_ih2, b_ih2, b_hh2, a,
                                      MROWS, HH, HH, HH);
    }
    // 4) layer-2 recurrence -> H2
    rec_kernel<<<128, 320>>>(W_hh2, a, h2);

    // 5) projections (permuted store: m = s*32+b -> row b*512+s)
    {
        dim3 grid((NOUT + 63) / 64, MROWS / 128);
        gemm_nt<true><<<grid, 256>>>(h1, fc1_w, fc1_b, nullptr, out,
                                     MROWS, NOUT, HH, NOUT);
        gemm_nt<true><<<grid, 256>>>(h2, fc2_w, fc2_b, nullptr,
                                     out + (size_t)MROWS * NOUT,
                                     MROWS, NOUT, HH, NOUT);
    }
}

// round 5
// speedup vs baseline: 1.3893x; 1.3893x over previous
#include <cuda_runtime.h>
#include <cuda_bf16.h>

// Problem dims
#define BB    32
#define SS    512
#define WIN   5
#define EMB   300
#define HH    300
#define K1    1500        // EMB*WIN
#define NOUT  128
#define MROWS (BB*SS)     // 16384

// ------------------------------------------------------------------
// Scratch (static device globals)
// ------------------------------------------------------------------
__device__ float g_XE[(size_t)MROWS * K1];   // relu(embedded)
__device__ float g_A [(size_t)MROWS * HH];   // pre-activation (A1 then A2)
__device__ float g_H1[(size_t)MROWS * HH];   // layer1 hidden states [s*32+b][300]
__device__ float g_H2[(size_t)MROWS * HH];   // layer2 hidden states

// ------------------------------------------------------------------
// helpers
// ------------------------------------------------------------------
__device__ __forceinline__ void ffma2(unsigned long long &d,
                                      unsigned long long a,
                                      unsigned long long b) {
    asm("fma.rn.f32x2 %0, %1, %2, %0;" : "+l"(d) : "l"(a), "l"(b));
}
__device__ __forceinline__ unsigned long long pack2(float lo, float hi) {
    unsigned long long r;
    asm("mov.b64 %0, {%1, %2};" : "=l"(r) : "f"(lo), "f"(hi));
    return r;
}
__device__ __forceinline__ void unpack2(unsigned long long v, float &lo, float &hi) {
    asm("mov.b64 {%0, %1}, %2;" : "=f"(lo), "=f"(hi) : "l"(v));
}
__device__ __forceinline__ unsigned smem_u32(const void *p) {
    unsigned a;
    asm("{ .reg .u64 t; cvta.to.shared.u64 t, %1; cvt.u32.u64 %0, t; }"
        : "=r"(a) : "l"(p));
    return a;
}
// tanh via MUFU: 1 - 2/(exp2(2x*log2e)+1). abs err ~1e-7, no division.
__device__ __forceinline__ float tanh_fast(float x) {
    float e;
    asm("ex2.approx.f32 %0, %1;" : "=f"(e) : "f"(x * 2.88539008177792681f));
    float r;
    asm("rcp.approx.f32 %0, %1;" : "=f"(r) : "f"(e + 1.0f));
    return fmaf(-2.0f, r, 1.0f);
}

// ------------------------------------------------------------------
// Kernel 1: embedding gather + relu (proven fast path from R2)
// ------------------------------------------------------------------
__global__ void embed_kernel(const int *__restrict__ x,
                             const float *__restrict__ emb) {
    int m = blockIdx.x;            // m = s*32 + b
    int s = m >> 5, b = m & 31;
    __shared__ int idx[WIN];
    if (threadIdx.x < WIN) idx[threadIdx.x] = x[(b * SS + s) * WIN + threadIdx.x];
    __syncthreads();
    float4 *out4 = reinterpret_cast<float4 *>(g_XE + (size_t)m * K1);
    for (int i = threadIdx.x; i < K1 / 4; i += blockDim.x) {
        int e4 = i * 4;
        int w = e4 / EMB;
        int e = e4 - w * EMB;
        float4 v = *reinterpret_cast<const float4 *>(emb + (size_t)idx[w] * EMB + e);
        v.x = fmaxf(v.x, 0.f); v.y = fmaxf(v.y, 0.f);
        v.z = fmaxf(v.z, 0.f); v.w = fmaxf(v.w, 0.f);
        out4[i] = v;
    }
}

// ------------------------------------------------------------------
// GEMM: C[m][n] = sum_k A[m][k]*Bw[n][k] + b1[n] (+ b2[n])
// BM=128, BN=64, BK=16, 256 threads, 4x8 thread tile via f32x2.
// ------------------------------------------------------------------
template <bool PERM>
__global__ __launch_bounds__(256)
void gemm_nt(const float *__restrict__ A, const float *__restrict__ Bw,
             const float *__restrict__ b1, const float *__restrict__ b2,
             float *__restrict__ C, int M, int N, int K, int ldc) {
    __shared__ __align__(16) float As[16][132];
    __shared__ __align__(16) float Bs[16][68];

    const int tid = threadIdx.x;
    const int m0 = blockIdx.y * 128;
    const int n0 = blockIdx.x * 64;
    const int tx = tid & 7;
    const int ty = tid >> 3;
    const int a_r = tid >> 2;
    const int a_k = (tid & 3) * 4;

    unsigned long long acc[4][4];
#pragma unroll
    for (int i = 0; i < 4; i++)
#pragma unroll
        for (int j = 0; j < 4; j++) acc[i][j] = 0ULL;

    const int KT = (K + 15) >> 4;
    for (int kt = 0; kt < KT; kt++) {
        int k0 = kt * 16;
        float4 av0 = make_float4(0.f, 0.f, 0.f, 0.f);
        float4 av1 = av0, bv = av0;
        int kk = k0 + a_k;
        if (kk < K) {
            av0 = *reinterpret_cast<const float4 *>(A + (size_t)(m0 + a_r) * K + kk);
            av1 = *reinterpret_cast<const float4 *>(A + (size_t)(m0 + a_r + 64) * K + kk);
            if (n0 + a_r < N)
                bv = *reinterpret_cast<const float4 *>(Bw + (size_t)(n0 + a_r) * K + kk);
        }
        __syncthreads();
        As[a_k + 0][a_r] = av0.x; As[a_k + 1][a_r] = av0.y;
        As[a_k + 2][a_r] = av0.z; As[a_k + 3][a_r] = av0.w;
        As[a_k + 0][a_r + 64] = av1.x; As[a_k + 1][a_r + 64] = av1.y;
        As[a_k + 2][a_r + 64] = av1.z; As[a_k + 3][a_r + 64] = av1.w;
        Bs[a_k + 0][a_r] = bv.x; Bs[a_k + 1][a_r] = bv.y;
        Bs[a_k + 2][a_r] = bv.z; Bs[a_k + 3][a_r] = bv.w;
        __syncthreads();

#pragma unroll
        for (int k = 0; k < 16; k++) {
            float4 a4 = *reinterpret_cast<const float4 *>(&As[k][ty * 4]);
            const ulonglong2 *bp =
                reinterpret_cast<const ulonglong2 *>(&Bs[k][tx * 8]);
            ulonglong2 bA = bp[0], bB = bp[1];
            unsigned long long a0 = pack2(a4.x, a4.x);
            unsigned long long a1 = pack2(a4.y, a4.y);
            unsigned long long a2 = pack2(a4.z, a4.z);
            unsigned long long a3 = pack2(a4.w, a4.w);
            ffma2(acc[0][0], a0, bA.x); ffma2(acc[0][1], a0, bA.y);
            ffma2(acc[0][2], a0, bB.x); ffma2(acc[0][3], a0, bB.y);
            ffma2(acc[1][0], a1, bA.x); ffma2(acc[1][1], a1, bA.y);
            ffma2(acc[1][2], a1, bB.x); ffma2(acc[1][3], a1, bB.y);
            ffma2(acc[2][0], a2, bA.x); ffma2(acc[2][1], a2, bA.y);
            ffma2(acc[2][2], a2, bB.x); ffma2(acc[2][3], a2, bB.y);
            ffma2(acc[3][0], a3, bA.x); ffma2(acc[3][1], a3, bA.y);
            ffma2(acc[3][2], a3, bB.x); ffma2(acc[3][3], a3, bB.y);
        }
    }

    float bias[8];
#pragma unroll
    for (int jj = 0; jj < 8; jj++) {
        int n = n0 + tx * 8 + jj;
        bias[jj] = (n < N) ? (b1[n] + (b2 ? b2[n] : 0.f)) : 0.f;
    }
#pragma unroll
    for (int i = 0; i < 4; i++) {
        int m = m0 + ty * 4 + i;
        int row = PERM ? ((m & 31) * SS + (m >> 5)) : m;
        float *cp = C + (size_t)row * ldc;
#pragma unroll
        for (int j = 0; j < 4; j++) {
            int n = n0 + tx * 8 + 2 * j;
            float lo, hi;
            unpack2(acc[i][j], lo, hi);
            if (n < N)     cp[n]     = lo + bias[2 * j];
            if (n + 1 < N) cp[n + 1] = hi + bias[2 * j + 1];
        }
    }
}

// ------------------------------------------------------------------
// Recurrence, K-split: one batch element per 4-CTA cluster.
// CTA r holds W[:, 75r:75r+75] (all 300 rows x its 75-col slice) in regs.
// Per step: each thread j computes partial_j = dot(W[j, slice_r], h_slice_r)
// using ONLY the local h chunk (rows owned == cols needed -> no h broadcast),
// then pushes one f32 via st.async (tx-counted on the owner's mbarrier).
// Owner CTA waits for 1200 tx bytes (4x75x4B), sums 4 partials + A, tanh.
// ------------------------------------------------------------------
__global__ void __cluster_dims__(4, 1, 1) __launch_bounds__(320)
rec_kernel(const float *__restrict__ W, const float *__restrict__ A,
           float *__restrict__ Hout) {
    __shared__ __align__(16) float hloc[2][80];    // my h chunk (75 + zero pad)
    __shared__ __align__(16) float ps[2][4][80];   // [buf][srcCTA][slot]
    __shared__ __align__(8) unsigned long long mbar[2];

    const int tid  = threadIdx.x;
    const int rank = blockIdx.x & 3;
    const int b    = blockIdx.x >> 2;
    const bool active = tid < 300;
    const int dst  = active ? (tid / 75) : 0;    // owner CTA of row tid
    const int slot = active ? (tid % 75) : 0;

    // W column-slice: thread j holds W[j, 75*rank .. 75*rank+74], packed f32x2.
    unsigned long long w2[38];
    if (active) {
        const float *wp = W + (size_t)tid * HH + rank * 75;
#pragma unroll
        for (int i = 0; i < 37; i++) w2[i] = pack2(wp[2 * i], wp[2 * i + 1]);
        w2[37] = pack2(wp[74], 0.f);
    }
    // zero h buffers (pads must stay 0: 0 * w = 0 in the dot)
    for (int i = tid; i < 2 * 80; i += blockDim.x) (&hloc[0][0])[i] = 0.f;

    if (tid == 0) {
        unsigned m0 = smem_u32(&mbar[0]), m1 = smem_u32(&mbar[1]);
        asm volatile("mbarrier.init.shared.b64 [%0], 1;" :: "r"(m0) : "memory");
        asm volatile("mbarrier.init.shared.b64 [%0], 1;" :: "r"(m1) : "memory");
        // pre-arm both phases: 1 arrival + 1200 tx bytes each
        asm volatile("mbarrier.arrive.expect_tx.shared.b64 _, [%0], 1200;"
                     :: "r"(m0) : "memory");
        asm volatile("mbarrier.arrive.expect_tx.shared.b64 _, [%0], 1200;"
                     :: "r"(m1) : "memory");
    }
    __syncthreads();
    asm volatile("barrier.cluster.arrive.aligned;" ::: "memory");
    asm volatile("barrier.cluster.wait.aligned;" ::: "memory");

    // loop-invariant remote addresses (dest CTA fixed per thread)
    unsigned ps_rem[2], mb_rem[2];
    if (active) {
#pragma unroll
        for (int p = 0; p < 2; p++) {
            unsigned lp = smem_u32(&ps[p][rank][slot]);
            unsigned lm = smem_u32(&mbar[p]);
            asm("mapa.shared::cluster.u32 %0, %1, %2;" : "=r"(ps_rem[p]) : "r"(lp), "r"(dst));
            asm("mapa.shared::cluster.u32 %0, %1, %2;" : "=r"(mb_rem[p]) : "r"(lm), "r"(dst));
        }
    }
    unsigned mb_loc[2] = { smem_u32(&mbar[0]), smem_u32(&mbar[1]) };

    const float *arow = A + (size_t)b * HH + rank * 75;   // + t*BB*HH + jr
    float *hrow = Hout + (size_t)b * HH + rank * 75;

    float a_cur = (tid < 75) ? arow[tid] : 0.f;

    for (int t = 0; t < SS; t++) {
        const int pb = t & 1;
        // prefetch next A (off critical path)
        float a_nxt = 0.f;
        if (tid < 75 && t + 1 < SS)
            a_nxt = arow[(size_t)(t + 1) * BB * HH + tid];

        if (active) {
            // partial_j = dot(W[j, slice], h_slice(t-1));  h(t-1) in hloc[pb^1]
            const ulonglong2 *hp2 =
                reinterpret_cast<const ulonglong2 *>(&hloc[pb ^ 1][0]);
            unsigned long long acc0 = 0ULL, acc1 = 0ULL;
#pragma unroll
            for (int k = 0; k < 19; k++) {
                ulonglong2 hv = hp2[k];
                if (k & 1) { ffma2(acc1, w2[2 * k], hv.x); ffma2(acc1, w2[2 * k + 1], hv.y); }
                else       { ffma2(acc0, w2[2 * k], hv.x); ffma2(acc0, w2[2 * k + 1], hv.y); }
            }
            float l0, h0, l1, h1;
            unpack2(acc0, l0, h0); unpack2(acc1, l1, h1);
            float p = (l0 + h0) + (l1 + h1);
            // push partial to owner (tx-counted store; no per-thread arrive)
            asm volatile(
                "st.async.shared::cluster.mbarrier::complete_tx::bytes.b32 [%0], %1, [%2];"
                :: "r"(ps_rem[pb]), "r"(__float_as_uint(p)), "r"(mb_rem[pb])
                : "memory");
        }

        if (tid < 75) {
            // wait for all 300 partials of my 75 rows (4 x 75 x 4B = 1200B)
            unsigned par = (t >> 1) & 1;
            asm volatile(
                "{\n\t.reg .pred P;\n"
                "RW%=:\n\t"
                "mbarrier.try_wait.parity.acquire.cluster.shared::cta.b64 P, [%0], %1;\n\t"
                "@!P bra RW%=;\n\t}"
                :: "r"(mb_loc[pb]), "r"(par) : "memory");
            if (tid == 0) {   // re-arm this barrier for step t+2
                asm volatile("mbarrier.arrive.expect_tx.shared.b64 _, [%0], 1200;"
                             :: "r"(mb_loc[pb]) : "memory");
            }
            float s = ps[pb][0][tid] + ps[pb][1][tid] +
                      ps[pb][2][tid] + ps[pb][3][tid] + a_cur;
            float hv = tanh_fast(s);
            hrow[(size_t)t * BB * HH + tid] = hv;
            hloc[pb][tid] = hv;
        }
        a_cur = a_nxt;
        __syncthreads();   // publish hloc[pb] to all threads for step t+1
    }

    // peers may still have in-flight st.async into our SMEM until all finish
    asm volatile("barrier.cluster.arrive.aligned;" ::: "memory");
    asm volatile("barrier.cluster.wait.aligned;" ::: "memory");
}

// ------------------------------------------------------------------
// Launch sequence
// ------------------------------------------------------------------
extern "C" void kernel_launch(void *const *d_in, const int *in_sizes, int n_in,
                              void *d_out, int out_size) {
    const int   *x     = (const int *)d_in[0];
    const float *emb   = (const float *)d_in[1];
    const float *W_ih1 = (const float *)d_in[2];
    const float *W_hh1 = (const float *)d_in[3];
    const float *b_ih1 = (const float *)d_in[4];
    const float *b_hh1 = (const float *)d_in[5];
    const float *W_ih2 = (const float *)d_in[6];
    const float *W_hh2 = (const float *)d_in[7];
    const float *b_ih2 = (const float *)d_in[8];
    const float *b_hh2 = (const float *)d_in[9];
    const float *fc1_w = (const float *)d_in[10];
    const float *fc1_b = (const float *)d_in[11];
    const float *fc2_w = (const float *)d_in[12];
    const float *fc2_b = (const float *)d_in[13];
    float *out = (float *)d_out;

    float *xe, *a, *h1, *h2;
    cudaGetSymbolAddress((void **)&xe, g_XE);
    cudaGetSymbolAddress((void **)&a,  g_A);
    cudaGetSymbolAddress((void **)&h1, g_H1);
    cudaGetSymbolAddress((void **)&h2, g_H2);

    // 1) embed + relu
    embed_kernel<<<MROWS, 128>>>(x, emb);

    // 2) A1 = XE @ W_ih1^T + (b_ih1 + b_hh1)
    {
        dim3 grid((HH + 63) / 64, MROWS / 128);
        gemm_nt<false><<<grid, 256>>>(xe, W_ih1, b_ih1, b_hh1, a,
                                      MROWS, HH, K1, HH);
    }
    // 3) layer-1 recurrence -> H1
    rec_kernel<<<128, 320>>>(W_hh1, a, h1);

    // 4) A2 = H1 @ W_ih2^T + (b_ih2 + b_hh2)
    {
        dim3 grid((HH + 63) / 64, MROWS / 128);
        gemm_nt<false><<<grid, 256>>>(h1, W_ih2, b_ih2, b_hh2, a,
                                      MROWS, HH, HH, HH);
    }
    // 5) layer-2 recurrence -> H2
    rec_kernel<<<128, 320>>>(W_hh2, a, h2);

    // 6) projections (permuted store: m = s*32+b -> row b*512+s)
    {
        dim3 grid((NOUT + 63) / 64, MROWS / 128);
        gemm_nt<true><<<grid, 256>>>(h1, fc1_w, fc1_b, nullptr, out,
                                     MROWS, NOUT, HH, NOUT);
        gemm_nt<true><<<grid, 256>>>(h2, fc2_w, fc2_b, nullptr,
                                     out + (size_t)MROWS * NOUT,
                                     MROWS, NOUT, HH, NOUT);
    }
}